// round 1
// baseline (speedup 1.0000x reference)
#include <cuda_runtime.h>
#include <cstdint>

// Problem constants
#define B_DIM 512
#define T_DIM 128
#define D_DIM 300
#define H_DIM 1024

typedef unsigned long long u64;

// Persistent state (static device globals; no allocation)
__device__ float g_h0[2][B_DIM * H_DIM];
__device__ float g_h1[2][B_DIM * H_DIM];
__device__ float g_c0[B_DIM * H_DIM];
__device__ float g_c1[B_DIM * H_DIM];
__device__ float g_acc[B_DIM * H_DIM];

// ---------- packed f32x2 helpers (Blackwell sm_100+) ----------
__device__ __forceinline__ u64 pack2(float lo, float hi) {
    u64 r;
    asm("mov.b64 %0, {%1, %2};" : "=l"(r) : "f"(lo), "f"(hi));
    return r;
}
__device__ __forceinline__ float2 unpack2(u64 v) {
    float2 r;
    asm("mov.b64 {%0, %1}, %2;" : "=f"(r.x), "=f"(r.y) : "l"(v));
    return r;
}
__device__ __forceinline__ u64 fma2(u64 a, u64 b, u64 c) {
    u64 d;
    asm("fma.rn.f32x2 %0, %1, %2, %3;" : "=l"(d) : "l"(a), "l"(b), "l"(c));
    return d;
}

// ---------- activations (fp32, MUFU-based, safe at extremes) ----------
__device__ __forceinline__ float sigf(float x) {
    return __fdividef(1.0f, 1.0f + __expf(-x));
}
__device__ __forceinline__ float tanhf_(float x) {
    // tanh(x) = 1 - 2/(exp(2x)+1); safe for |x| large (exp->inf or ->0)
    return 1.0f - 2.0f * __fdividef(1.0f, 1.0f + __expf(2.0f * x));
}

// ---------- GEMM mainloop over two concatenated K sources ----------
// Computes, for this CTA tile (64 batches x 16 units x 4 gates):
//   acc[mpair][gate] += sum_k A(src)[m, k] * W(src)[gate*H + u0 + u, k]
// Tile: BM=64, BN=64 (16 units * 4 interleaved gates), BK=16, 128 threads.
// Thread (tx = tid&15, ty = tid>>4) owns 8 batches (ty*8..+7, packed in f32x2
// pairs) of unit u0+tx, all 4 gates.
struct Src {
    const float* A;   // row m element k at A[m*lda + k]
    long lda;
    const float* W;   // row r element k at W[r*ldw + k]
    long ldw;
    int K;            // true K (guards applied when not multiple of 16)
};

__device__ __forceinline__ void gemm2(Src s0, Src s1, int u0,
                                      u64 acc[4][4], float* As, float* Ws) {
    const int tid = threadIdx.x;
    const int lm = tid & 63;     // A tile row (batch within tile)
    const int kh = tid >> 6;     // 0/1: which half of the 16-wide k slab
    const int nn = tid & 63;     // W tile col (unit*4 + gate)
    const int uu = nn >> 2;
    const int gg = nn & 3;
    const int tx = tid & 15;
    const int ty = tid >> 4;

    const int NT0 = (s0.K + 15) >> 4;
    const int NT1 = (s1.K + 15) >> 4;
    const int NT = NT0 + NT1;

    float ra[8], rw[8];

    auto load = [&](int kt) {
        const Src& s = (kt < NT0) ? s0 : s1;
        const int kt_l = (kt < NT0) ? kt : (kt - NT0);
        const int kbase = kt_l * 16 + kh * 8;
        const float* arow = s.A + (long)lm * s.lda;
        const float* wrow = s.W + ((long)(gg * H_DIM + u0 + uu)) * s.ldw;
#pragma unroll
        for (int j = 0; j < 8; j++) {
            const int k = kbase + j;
            const bool ok = (k < s.K);
            ra[j] = ok ? arow[k] : 0.0f;
            rw[j] = ok ? wrow[k] : 0.0f;
        }
    };

    load(0);
    for (int kt = 0; kt < NT; ++kt) {
        __syncthreads();  // previous tile's compute done
#pragma unroll
        for (int j = 0; j < 8; j++) {
            As[(kh * 8 + j) * 64 + lm] = ra[j];
            Ws[(kh * 8 + j) * 64 + nn] = rw[j];
        }
        __syncthreads();  // tile visible
        if (kt + 1 < NT) load(kt + 1);  // prefetch next slab into regs
#pragma unroll
        for (int k = 0; k < 16; k++) {
            ulonglong2 qa0 = *reinterpret_cast<const ulonglong2*>(As + k * 64 + ty * 8);
            ulonglong2 qa1 = *reinterpret_cast<const ulonglong2*>(As + k * 64 + ty * 8 + 4);
            float4 w = *reinterpret_cast<const float4*>(Ws + k * 64 + tx * 4);
            u64 w0 = pack2(w.x, w.x);
            u64 w1 = pack2(w.y, w.y);
            u64 w2 = pack2(w.z, w.z);
            u64 w3 = pack2(w.w, w.w);
            acc[0][0] = fma2(qa0.x, w0, acc[0][0]);
            acc[0][1] = fma2(qa0.x, w1, acc[0][1]);
            acc[0][2] = fma2(qa0.x, w2, acc[0][2]);
            acc[0][3] = fma2(qa0.x, w3, acc[0][3]);
            acc[1][0] = fma2(qa0.y, w0, acc[1][0]);
            acc[1][1] = fma2(qa0.y, w1, acc[1][1]);
            acc[1][2] = fma2(qa0.y, w2, acc[1][2]);
            acc[1][3] = fma2(qa0.y, w3, acc[1][3]);
            acc[2][0] = fma2(qa1.x, w0, acc[2][0]);
            acc[2][1] = fma2(qa1.x, w1, acc[2][1]);
            acc[2][2] = fma2(qa1.x, w2, acc[2][2]);
            acc[2][3] = fma2(qa1.x, w3, acc[2][3]);
            acc[3][0] = fma2(qa1.y, w0, acc[3][0]);
            acc[3][1] = fma2(qa1.y, w1, acc[3][1]);
            acc[3][2] = fma2(qa1.y, w2, acc[3][2]);
            acc[3][3] = fma2(qa1.y, w3, acc[3][3]);
        }
    }
}

// ---------- layer 0 step: gates = x_t @ Wih0^T + h0 @ Whh0^T + b ----------
__global__ void __launch_bounds__(128, 4)
lstm_step0(const float* __restrict__ x, const float* __restrict__ Wih0,
           const float* __restrict__ Whh0, const float* __restrict__ bih0,
           const float* __restrict__ bhh0, int t, int pp) {
    __shared__ __align__(16) float As[16 * 64];
    __shared__ __align__(16) float Ws[16 * 64];
    const int u0 = blockIdx.x * 16;
    const int m0 = blockIdx.y * 64;

    u64 acc[4][4];
#pragma unroll
    for (int j = 0; j < 4; j++)
#pragma unroll
        for (int g = 0; g < 4; g++) acc[j][g] = 0ull;

    Src s0;
    s0.A = x + (long)m0 * (T_DIM * D_DIM) + (long)t * D_DIM;
    s0.lda = (long)T_DIM * D_DIM;
    s0.W = Wih0; s0.ldw = D_DIM; s0.K = D_DIM;
    Src s1;
    s1.A = g_h0[pp] + (long)m0 * H_DIM;
    s1.lda = H_DIM;
    s1.W = Whh0; s1.ldw = H_DIM; s1.K = H_DIM;

    gemm2(s0, s1, u0, acc, As, Ws);

    const int tx = threadIdx.x & 15;
    const int ty = threadIdx.x >> 4;
    const int ucol = u0 + tx;
    const float bi = bih0[ucol] + bhh0[ucol];
    const float bf = bih0[H_DIM + ucol] + bhh0[H_DIM + ucol];
    const float bg = bih0[2 * H_DIM + ucol] + bhh0[2 * H_DIM + ucol];
    const float bo = bih0[3 * H_DIM + ucol] + bhh0[3 * H_DIM + ucol];
    float* __restrict__ hnext = g_h0[pp ^ 1];
#pragma unroll
    for (int j = 0; j < 4; j++) {
        float2 vi = unpack2(acc[j][0]);
        float2 vf = unpack2(acc[j][1]);
        float2 vg = unpack2(acc[j][2]);
        float2 vo = unpack2(acc[j][3]);
        const int bb = m0 + ty * 8 + 2 * j;
#pragma unroll
        for (int l = 0; l < 2; l++) {
            const int b = bb + l;
            const long idx = (long)b * H_DIM + ucol;
            const float iv = (l ? vi.y : vi.x) + bi;
            const float fv = (l ? vf.y : vf.x) + bf;
            const float gv = (l ? vg.y : vg.x) + bg;
            const float ov = (l ? vo.y : vo.x) + bo;
            const float c = g_c0[idx];
            const float cn = sigf(fv) * c + sigf(iv) * tanhf_(gv);
            const float hn = sigf(ov) * tanhf_(cn);
            g_c0[idx] = cn;
            hnext[idx] = hn;
        }
    }
}

// ---------- layer 1 step: gates = h0_cur @ Wih1^T + h1 @ Whh1^T + b ----------
__global__ void __launch_bounds__(128, 4)
lstm_step1(const float* __restrict__ Wih1, const float* __restrict__ Whh1,
           const float* __restrict__ bih1, const float* __restrict__ bhh1,
           int pp) {
    __shared__ __align__(16) float As[16 * 64];
    __shared__ __align__(16) float Ws[16 * 64];
    const int u0 = blockIdx.x * 16;
    const int m0 = blockIdx.y * 64;

    u64 acc[4][4];
#pragma unroll
    for (int j = 0; j < 4; j++)
#pragma unroll
        for (int g = 0; g < 4; g++) acc[j][g] = 0ull;

    Src s0;
    s0.A = g_h0[pp ^ 1] + (long)m0 * H_DIM;  // h0 written by this step's layer0
    s0.lda = H_DIM;
    s0.W = Wih1; s0.ldw = H_DIM; s0.K = H_DIM;
    Src s1;
    s1.A = g_h1[pp] + (long)m0 * H_DIM;
    s1.lda = H_DIM;
    s1.W = Whh1; s1.ldw = H_DIM; s1.K = H_DIM;

    gemm2(s0, s1, u0, acc, As, Ws);

    const int tx = threadIdx.x & 15;
    const int ty = threadIdx.x >> 4;
    const int ucol = u0 + tx;
    const float bi = bih1[ucol] + bhh1[ucol];
    const float bf = bih1[H_DIM + ucol] + bhh1[H_DIM + ucol];
    const float bg = bih1[2 * H_DIM + ucol] + bhh1[2 * H_DIM + ucol];
    const float bo = bih1[3 * H_DIM + ucol] + bhh1[3 * H_DIM + ucol];
    float* __restrict__ hnext = g_h1[pp ^ 1];
#pragma unroll
    for (int j = 0; j < 4; j++) {
        float2 vi = unpack2(acc[j][0]);
        float2 vf = unpack2(acc[j][1]);
        float2 vg = unpack2(acc[j][2]);
        float2 vo = unpack2(acc[j][3]);
        const int bb = m0 + ty * 8 + 2 * j;
#pragma unroll
        for (int l = 0; l < 2; l++) {
            const int b = bb + l;
            const long idx = (long)b * H_DIM + ucol;
            const float iv = (l ? vi.y : vi.x) + bi;
            const float fv = (l ? vf.y : vf.x) + bf;
            const float gv = (l ? vg.y : vg.x) + bg;
            const float ov = (l ? vo.y : vo.x) + bo;
            const float c = g_c1[idx];
            const float cn = sigf(fv) * c + sigf(iv) * tanhf_(gv);
            const float hn = sigf(ov) * tanhf_(cn);
            g_c1[idx] = cn;
            hnext[idx] = hn;
            g_acc[idx] += hn;
        }
    }
}

// ---------- init: zero all persistent state ----------
__global__ void init_k() {
    const long n = (long)B_DIM * H_DIM;
    long i = (long)blockIdx.x * blockDim.x + threadIdx.x;
    const long stride = (long)gridDim.x * blockDim.x;
    for (; i < n; i += stride) {
        g_h0[0][i] = 0.0f;
        g_h0[1][i] = 0.0f;
        g_h1[0][i] = 0.0f;
        g_h1[1][i] = 0.0f;
        g_c0[i] = 0.0f;
        g_c1[i] = 0.0f;
        g_acc[i] = 0.0f;
    }
}

// ---------- finalize: out[b] = (acc[b,:]/T) . Wdec + bdec ----------
__global__ void finalize_k(const float* __restrict__ Wdec,
                           const float* __restrict__ bdec,
                           float* __restrict__ out) {
    const int b = blockIdx.x;
    const int tid = threadIdx.x;  // 128
    float p = 0.0f;
    for (int u = tid; u < H_DIM; u += 128)
        p += g_acc[(long)b * H_DIM + u] * Wdec[u];
#pragma unroll
    for (int o = 16; o; o >>= 1) p += __shfl_down_sync(0xffffffffu, p, o);
    __shared__ float red[4];
    if ((tid & 31) == 0) red[tid >> 5] = p;
    __syncthreads();
    if (tid == 0) {
        const float s = red[0] + red[1] + red[2] + red[3];
        out[b] = s * (1.0f / (float)T_DIM) + bdec[0];
    }
}

extern "C" void kernel_launch(void* const* d_in, const int* in_sizes, int n_in,
                              void* d_out, int out_size) {
    const float* x    = (const float*)d_in[0];
    const float* Wih0 = (const float*)d_in[1];
    const float* Whh0 = (const float*)d_in[2];
    const float* bih0 = (const float*)d_in[3];
    const float* bhh0 = (const float*)d_in[4];
    const float* Wih1 = (const float*)d_in[5];
    const float* Whh1 = (const float*)d_in[6];
    const float* bih1 = (const float*)d_in[7];
    const float* bhh1 = (const float*)d_in[8];
    const float* Wdec = (const float*)d_in[9];
    const float* bdec = (const float*)d_in[10];
    float* out = (float*)d_out;

    init_k<<<512, 256>>>();

    dim3 grid(64, 8);  // x: unit tiles (1024/16), y: batch tiles (512/64)
    for (int t = 0; t < T_DIM; ++t) {
        const int pp = t & 1;
        lstm_step0<<<grid, 128>>>(x, Wih0, Whh0, bih0, bhh0, t, pp);
        lstm_step1<<<grid, 128>>>(Wih1, Whh1, bih1, bhh1, pp);
    }

    finalize_k<<<B_DIM, 128>>>(Wdec, bdec, out);
}

// round 3
// speedup vs baseline: 5.0091x; 5.0091x over previous
#include <cuda_runtime.h>
#include <cuda_bf16.h>
#include <cstdint>

#define B_DIM 512
#define T_DIM 128
#define D_DIM 300
#define DPAD  320
#define H_DIM 1024

typedef uint32_t u32;
typedef uint64_t u64;

// ------------------------------------------------------------------
// Persistent device buffers (static globals; no runtime allocation)
// split-bf16 operands: layout [row][2*K]: hi at [0,K), lo at [K,2K)
// ------------------------------------------------------------------
__device__ __align__(16) __nv_bfloat16 g_x2[(size_t)B_DIM * T_DIM * 2 * DPAD];
__device__ __align__(16) __nv_bfloat16 g_wih0[(size_t)4 * H_DIM * 2 * DPAD];
__device__ __align__(16) __nv_bfloat16 g_whh0[(size_t)4 * H_DIM * 2 * H_DIM];
__device__ __align__(16) __nv_bfloat16 g_wih1[(size_t)4 * H_DIM * 2 * H_DIM];
__device__ __align__(16) __nv_bfloat16 g_whh1[(size_t)4 * H_DIM * 2 * H_DIM];
__device__ __align__(16) __nv_bfloat16 g_h0b[2][(size_t)B_DIM * 2 * H_DIM];
__device__ __align__(16) __nv_bfloat16 g_h1b[2][(size_t)B_DIM * 2 * H_DIM];
__device__ __align__(16) float g_c0[(size_t)B_DIM * H_DIM];
__device__ __align__(16) float g_c1[(size_t)B_DIM * H_DIM];
__device__ __align__(16) float g_acc[(size_t)B_DIM * H_DIM];

// ------------------------------------------------------------------
// Helpers (all sm_80-compatible: cp.async / ldmatrix / mma.sync)
// ------------------------------------------------------------------
__device__ __forceinline__ u32 smem_to_u32(const void* p) {
    u32 a;
    asm("{ .reg .u64 t; cvta.to.shared.u64 t, %1; cvt.u32.u64 %0, t; }" : "=r"(a) : "l"(p));
    return a;
}
__device__ __forceinline__ void cp16(u32 s, const void* g) {
    asm volatile("cp.async.cg.shared.global [%0], [%1], 16;" :: "r"(s), "l"(g));
}
#define CP_COMMIT() asm volatile("cp.async.commit_group;" ::: "memory")
#define CP_WAIT1()  asm volatile("cp.async.wait_group 1;" ::: "memory")
#define CP_WAIT0()  asm volatile("cp.async.wait_group 0;" ::: "memory")

__device__ __forceinline__ void ldsm4(u32 addr, u32* r) {
    asm volatile("ldmatrix.sync.aligned.m8n8.x4.shared.b16 {%0,%1,%2,%3}, [%4];"
                 : "=r"(r[0]), "=r"(r[1]), "=r"(r[2]), "=r"(r[3]) : "r"(addr));
}
__device__ __forceinline__ void mma_bf16(float* d, const u32* a, u32 b0, u32 b1) {
    asm volatile("mma.sync.aligned.m16n8k16.row.col.f32.bf16.bf16.f32 "
                 "{%0,%1,%2,%3}, {%4,%5,%6,%7}, {%8,%9}, {%0,%1,%2,%3};"
                 : "+f"(d[0]), "+f"(d[1]), "+f"(d[2]), "+f"(d[3])
                 : "r"(a[0]), "r"(a[1]), "r"(a[2]), "r"(a[3]), "r"(b0), "r"(b1));
}

// SMEM tile: [128 rows][32 bf16] = 64B/row, 4 x 16B chunks, swizzle chunk^(row&3)
__device__ __forceinline__ u32 swz(u32 row, u32 chunk) {
    return row * 64u + ((chunk ^ (row & 3u)) << 4);
}

__device__ __forceinline__ float sigf(float x) { return __fdividef(1.0f, 1.0f + __expf(-x)); }
__device__ __forceinline__ float tanhf_(float x) {
    return 1.0f - 2.0f * __fdividef(1.0f, 1.0f + __expf(2.0f * x));
}

#define TILE_B  8192           // one 128x32 bf16 tile
#define BUF_B   (4 * TILE_B)   // Ah, Al, Wh, Wl
#define SMEM_TOT (1024 + 2 * BUF_B)  // 66560

// ------------------------------------------------------------------
// Fused GEMM + LSTM-cell step kernel.
// CTA: 128 batches x 128 gate-cols (32 units). 8 warps (2 M x 4 N).
// gates col n -> W row (n&3)*H + u0 + (n>>2)  (gate-interleaved N)
// ------------------------------------------------------------------
__global__ void __launch_bounds__(256, 1)
lstm_step(int layer, int t, int pp,
          const float* __restrict__ bih, const float* __restrict__ bhh) {
    extern __shared__ __align__(16) char smem[];
    const u32 sb = smem_to_u32(smem);
    const int tid = threadIdx.x;
    const int lane = tid & 31;
    const int wid = tid >> 5;
    const int wm = wid >> 2;          // 0..1, 64 rows each
    const int wn = wid & 3;           // 0..3, 32 cols each
    const int u0 = blockIdx.x * 32;   // units
    const int m0 = blockIdx.y * 128;  // batches

    float* sbias = (float*)smem;      // [128]
    if (tid < 128) {
        const int wr = (tid & 3) * H_DIM + u0 + (tid >> 2);
        sbias[tid] = bih[wr] + bhh[wr];
    }

    // per-thread load row assignments
    const int r  = tid >> 1;          // tile row 0..127 (A: batch, W: col)
    const int c2 = (tid & 1) * 2;     // chunk pair 0/2
    const int wrow = (r & 3) * H_DIM + u0 + (r >> 2);

    const __nv_bfloat16 *Ar[2], *Wr[2];
    int loA[2], loW[2], nc0;
    if (layer == 0) {
        Ar[0] = g_x2 + (size_t)(m0 + r) * (T_DIM * 2 * DPAD) + (size_t)t * 2 * DPAD;
        loA[0] = DPAD;
        Wr[0] = g_wih0 + (size_t)wrow * 2 * DPAD;
        loW[0] = DPAD;
        nc0 = DPAD / 32;  // 10
        Ar[1] = g_h0b[pp] + (size_t)(m0 + r) * 2 * H_DIM;
        Wr[1] = g_whh0 + (size_t)wrow * 2 * H_DIM;
    } else {
        Ar[0] = g_h0b[pp ^ 1] + (size_t)(m0 + r) * 2 * H_DIM;  // h0 of this step
        loA[0] = H_DIM;
        Wr[0] = g_wih1 + (size_t)wrow * 2 * H_DIM;
        loW[0] = H_DIM;
        nc0 = H_DIM / 32;  // 32
        Ar[1] = g_h1b[pp] + (size_t)(m0 + r) * 2 * H_DIM;
        Wr[1] = g_whh1 + (size_t)wrow * 2 * H_DIM;
    }
    loA[1] = H_DIM; loW[1] = H_DIM;
    const int NC = nc0 + H_DIM / 32;

    const u32 s0 = sb + 1024 + swz(r, c2);
    const u32 s1 = sb + 1024 + swz(r, c2 + 1);

    float acc[4][4][4];
#pragma unroll
    for (int mi = 0; mi < 4; mi++)
#pragma unroll
        for (int nf = 0; nf < 4; nf++)
#pragma unroll
            for (int q = 0; q < 4; q++) acc[mi][nf][q] = 0.0f;

    // chunk loader: 8x cp.async 16B
    auto ldchunk = [&](int c, int buf) {
        const int sg = (c < nc0) ? 0 : 1;
        const int k0 = (c < nc0) ? c * 32 : (c - nc0) * 32;
        const __nv_bfloat16* pa = Ar[sg];
        const __nv_bfloat16* pw = Wr[sg];
        const int la = loA[sg], lw = loW[sg];
        const int e = k0 + c2 * 8;
        const u32 d = buf * BUF_B;
        cp16(s0 + d, pa + e);
        cp16(s1 + d, pa + e + 8);
        cp16(s0 + d + TILE_B, pa + la + e);
        cp16(s1 + d + TILE_B, pa + la + e + 8);
        cp16(s0 + d + 2 * TILE_B, pw + e);
        cp16(s1 + d + 2 * TILE_B, pw + e + 8);
        cp16(s0 + d + 3 * TILE_B, pw + lw + e);
        cp16(s1 + d + 3 * TILE_B, pw + lw + e + 8);
    };

    ldchunk(0, 0);
    CP_COMMIT();

    for (int c = 0; c < NC; c++) {
        if (c + 1 < NC) { ldchunk(c + 1, (c + 1) & 1); CP_COMMIT(); CP_WAIT1(); }
        else           { CP_WAIT0(); }
        __syncthreads();  // buf[c&1] visible to all

        const u32 bAh = sb + 1024 + (u32)(c & 1) * BUF_B;
        const u32 bAl = bAh + TILE_B;
        const u32 bWh = bAh + 2 * TILE_B;
        const u32 bWl = bAh + 3 * TILE_B;

#pragma unroll
        for (int kk = 0; kk < 2; kk++) {
            u32 ah[4][4], al[4][4], wh[2][4], wl[2][4];
            const u32 achunk = 2 * kk + (lane >> 4);
#pragma unroll
            for (int mi = 0; mi < 4; mi++) {
                const u32 row = wm * 64 + mi * 16 + (lane & 15);
                const u32 off = swz(row, achunk);
                ldsm4(bAh + off, ah[mi]);
                ldsm4(bAl + off, al[mi]);
            }
            const u32 wchunk = 2 * kk + ((lane >> 3) & 1);
#pragma unroll
            for (int nf2 = 0; nf2 < 2; nf2++) {
                const u32 row = wn * 32 + nf2 * 16 + (lane & 7) + ((lane >> 4) << 3);
                const u32 off = swz(row, wchunk);
                ldsm4(bWh + off, wh[nf2]);
                ldsm4(bWl + off, wl[nf2]);
            }
#pragma unroll
            for (int mi = 0; mi < 4; mi++)
#pragma unroll
                for (int nf = 0; nf < 4; nf++) {
                    const u32* H = wh[nf >> 1] + (nf & 1) * 2;
                    const u32* L = wl[nf >> 1] + (nf & 1) * 2;
                    mma_bf16(acc[mi][nf], ah[mi], H[0], H[1]);  // hi*hi
                    mma_bf16(acc[mi][nf], al[mi], H[0], H[1]);  // lo*hi
                    mma_bf16(acc[mi][nf], ah[mi], L[0], L[1]);  // hi*lo
                }
        }
        __syncthreads();  // done reading buf[c&1] before it is overwritten
    }

    // ---------------- fused LSTM epilogue ----------------
    // thread cols: cc = 2*(lane&3); even lanes (lane&1==0) hold gates (i,f),
    // partner lane^1 holds (g,o) of the same unit.
    float* cmem = layer ? g_c1 : g_c0;
    __nv_bfloat16* hout = (layer ? g_h1b[pp ^ 1] : g_h0b[pp ^ 1]);
    const bool owner = ((lane & 1) == 0);
    const int cc = 2 * (lane & 3);

#pragma unroll
    for (int mi = 0; mi < 4; mi++)
#pragma unroll
        for (int nf = 0; nf < 4; nf++) {
            float v0 = acc[mi][nf][0], v1 = acc[mi][nf][1];
            float v2 = acc[mi][nf][2], v3 = acc[mi][nf][3];
            const float p0 = __shfl_xor_sync(0xffffffffu, v0, 1);
            const float p1 = __shfl_xor_sync(0xffffffffu, v1, 1);
            const float p2 = __shfl_xor_sync(0xffffffffu, v2, 1);
            const float p3 = __shfl_xor_sync(0xffffffffu, v3, 1);
            if (owner) {
                const int nl = wn * 32 + nf * 8 + cc;     // CTA-local col of gate i
                const int ucol = u0 + (nl >> 2);
                const float bi = sbias[nl], bf = sbias[nl + 1];
                const float bg = sbias[nl + 2], bo = sbias[nl + 3];
                const int rowa = m0 + wm * 64 + mi * 16 + (lane >> 2);
#pragma unroll
                for (int rh = 0; rh < 2; rh++) {
                    const int b = rowa + rh * 8;
                    const float iv = (rh ? v2 : v0) + bi;
                    const float fv = (rh ? v3 : v1) + bf;
                    const float gv = (rh ? p2 : p0) + bg;
                    const float ov = (rh ? p3 : p1) + bo;
                    const size_t ci = (size_t)b * H_DIM + ucol;
                    const float cold = cmem[ci];
                    const float cn = sigf(fv) * cold + sigf(iv) * tanhf_(gv);
                    const float hn = sigf(ov) * tanhf_(cn);
                    cmem[ci] = cn;
                    const __nv_bfloat16 hi = __float2bfloat16(hn);
                    hout[(size_t)b * 2 * H_DIM + ucol] = hi;
                    hout[(size_t)b * 2 * H_DIM + H_DIM + ucol] =
                        __float2bfloat16(hn - __bfloat162float(hi));
                    if (layer) g_acc[ci] += hn;
                }
            }
        }
}

// ------------------------------------------------------------------
// Conversion / init / finalize kernels
// ------------------------------------------------------------------
__global__ void conv_w_k(const float* __restrict__ W, int K, int Kp, int sel) {
    __nv_bfloat16* out = (sel == 0) ? g_wih0 : (sel == 1) ? g_whh0
                        : (sel == 2) ? g_wih1 : g_whh1;
    const size_t n = (size_t)4 * H_DIM * Kp;
    for (size_t i = (size_t)blockIdx.x * blockDim.x + threadIdx.x; i < n;
         i += (size_t)gridDim.x * blockDim.x) {
        const size_t row = i / Kp;
        const int k = (int)(i % Kp);
        const float v = (k < K) ? W[row * K + k] : 0.0f;
        const __nv_bfloat16 hi = __float2bfloat16(v);
        out[row * 2 * Kp + k] = hi;
        out[row * 2 * Kp + Kp + k] = __float2bfloat16(v - __bfloat162float(hi));
    }
}

__global__ void conv_x_k(const float* __restrict__ x) {
    const size_t n = (size_t)B_DIM * T_DIM * DPAD;
    for (size_t i = (size_t)blockIdx.x * blockDim.x + threadIdx.x; i < n;
         i += (size_t)gridDim.x * blockDim.x) {
        const size_t bt = i / DPAD;
        const int k = (int)(i % DPAD);
        const float v = (k < D_DIM) ? x[bt * D_DIM + k] : 0.0f;
        const __nv_bfloat16 hi = __float2bfloat16(v);
        g_x2[bt * 2 * DPAD + k] = hi;
        g_x2[bt * 2 * DPAD + DPAD + k] = __float2bfloat16(v - __bfloat162float(hi));
    }
}

__global__ void init_k() {
    const size_t nh = (size_t)B_DIM * 2 * H_DIM;
    const size_t nf = (size_t)B_DIM * H_DIM;
    const size_t stride = (size_t)gridDim.x * blockDim.x;
    for (size_t i = (size_t)blockIdx.x * blockDim.x + threadIdx.x; i < nh; i += stride) {
        g_h0b[0][i] = __float2bfloat16(0.0f);
        g_h1b[0][i] = __float2bfloat16(0.0f);
    }
    for (size_t i = (size_t)blockIdx.x * blockDim.x + threadIdx.x; i < nf; i += stride) {
        g_c0[i] = 0.0f; g_c1[i] = 0.0f; g_acc[i] = 0.0f;
    }
}

__global__ void finalize_k(const float* __restrict__ Wdec,
                           const float* __restrict__ bdec, float* __restrict__ out) {
    const int b = blockIdx.x;
    const int tid = threadIdx.x;  // 128
    float p = 0.0f;
    for (int u = tid; u < H_DIM; u += 128)
        p += g_acc[(size_t)b * H_DIM + u] * Wdec[u];
#pragma unroll
    for (int o = 16; o; o >>= 1) p += __shfl_down_sync(0xffffffffu, p, o);
    __shared__ float red[4];
    if ((tid & 31) == 0) red[tid >> 5] = p;
    __syncthreads();
    if (tid == 0)
        out[b] = (red[0] + red[1] + red[2] + red[3]) * (1.0f / (float)T_DIM) + bdec[0];
}

// ------------------------------------------------------------------
extern "C" void kernel_launch(void* const* d_in, const int* in_sizes, int n_in,
                              void* d_out, int out_size) {
    const float* x    = (const float*)d_in[0];
    const float* Wih0 = (const float*)d_in[1];
    const float* Whh0 = (const float*)d_in[2];
    const float* bih0 = (const float*)d_in[3];
    const float* bhh0 = (const float*)d_in[4];
    const float* Wih1 = (const float*)d_in[5];
    const float* Whh1 = (const float*)d_in[6];
    const float* bih1 = (const float*)d_in[7];
    const float* bhh1 = (const float*)d_in[8];
    const float* Wdec = (const float*)d_in[9];
    const float* bdec = (const float*)d_in[10];
    float* out = (float*)d_out;

    static int configured = 0;
    cudaFuncSetAttribute(lstm_step, cudaFuncAttributeMaxDynamicSharedMemorySize, SMEM_TOT);
    (void)configured;

    init_k<<<512, 256>>>();
    conv_w_k<<<1024, 256>>>(Wih0, D_DIM, DPAD, 0);
    conv_w_k<<<2048, 256>>>(Whh0, H_DIM, H_DIM, 1);
    conv_w_k<<<2048, 256>>>(Wih1, H_DIM, H_DIM, 2);
    conv_w_k<<<2048, 256>>>(Whh1, H_DIM, H_DIM, 3);
    conv_x_k<<<4096, 256>>>(x);

    dim3 grid(32, 4);  // 32 unit-tiles x 4 batch-tiles = 128 CTAs
    for (int t = 0; t < T_DIM; ++t) {
        const int pp = t & 1;
        lstm_step<<<grid, 256, SMEM_TOT>>>(0, t, pp, bih0, bhh0);
        lstm_step<<<grid, 256, SMEM_TOT>>>(1, t, pp, bih1, bhh1);
    }
    finalize_k<<<B_DIM, 128>>>(Wdec, bdec, out);
}

// round 4
// speedup vs baseline: 8.1491x; 1.6269x over previous
#include <cuda_runtime.h>
#include <cuda_fp16.h>
#include <cstdint>

#define B_DIM 512
#define T_DIM 128
#define D_DIM 300
#define DPAD  320
#define H_DIM 1024

typedef uint32_t u32;

// ------------------------------------------------------------------
// Persistent device buffers (static globals; no runtime allocation)
// Activations: single fp16. Weights: split fp16 [row][2*K]: hi|lo.
// ------------------------------------------------------------------
__device__ __align__(16) __half g_x[(size_t)B_DIM * T_DIM * DPAD];
__device__ __align__(16) __half g_wih0[(size_t)4 * H_DIM * 2 * DPAD];
__device__ __align__(16) __half g_whh0[(size_t)4 * H_DIM * 2 * H_DIM];
__device__ __align__(16) __half g_wih1[(size_t)4 * H_DIM * 2 * H_DIM];
__device__ __align__(16) __half g_whh1[(size_t)4 * H_DIM * 2 * H_DIM];
__device__ __align__(16) __half g_h0b[2][(size_t)B_DIM * H_DIM];
__device__ __align__(16) __half g_h1b[2][(size_t)B_DIM * H_DIM];
__device__ __align__(16) float g_c0[(size_t)B_DIM * H_DIM];
__device__ __align__(16) float g_c1[(size_t)B_DIM * H_DIM];
__device__ __align__(16) float g_acc[(size_t)B_DIM * H_DIM];

// ------------------------------------------------------------------
// Helpers (sm_80-compatible: cp.async / ldmatrix / mma.sync)
// ------------------------------------------------------------------
__device__ __forceinline__ u32 smem_to_u32(const void* p) {
    u32 a;
    asm("{ .reg .u64 t; cvta.to.shared.u64 t, %1; cvt.u32.u64 %0, t; }" : "=r"(a) : "l"(p));
    return a;
}
__device__ __forceinline__ void cp16(u32 s, const void* g) {
    asm volatile("cp.async.cg.shared.global [%0], [%1], 16;" :: "r"(s), "l"(g));
}
#define CP_COMMIT() asm volatile("cp.async.commit_group;" ::: "memory")
#define CP_WAIT2()  asm volatile("cp.async.wait_group 2;" ::: "memory")
#define CP_WAIT1()  asm volatile("cp.async.wait_group 1;" ::: "memory")
#define CP_WAIT0()  asm volatile("cp.async.wait_group 0;" ::: "memory")

__device__ __forceinline__ void ldsm4(u32 addr, u32* r) {
    asm volatile("ldmatrix.sync.aligned.m8n8.x4.shared.b16 {%0,%1,%2,%3}, [%4];"
                 : "=r"(r[0]), "=r"(r[1]), "=r"(r[2]), "=r"(r[3]) : "r"(addr));
}
__device__ __forceinline__ void mma_f16(float* d, const u32* a, u32 b0, u32 b1) {
    asm volatile("mma.sync.aligned.m16n8k16.row.col.f32.f16.f16.f32 "
                 "{%0,%1,%2,%3}, {%4,%5,%6,%7}, {%8,%9}, {%0,%1,%2,%3};"
                 : "+f"(d[0]), "+f"(d[1]), "+f"(d[2]), "+f"(d[3])
                 : "r"(a[0]), "r"(a[1]), "r"(a[2]), "r"(a[3]), "r"(b0), "r"(b1));
}

// SMEM tile: [128 rows][64 fp16] = 128B/row = 8 x 16B chunks; swizzle q^(row&7)
__device__ __forceinline__ u32 swz(u32 row, u32 q) {
    return row * 128u + ((q ^ (row & 7u)) << 4);
}

__device__ __forceinline__ float sigf(float x) { return __fdividef(1.0f, 1.0f + __expf(-x)); }
__device__ __forceinline__ float tanhf_(float x) {
    return 1.0f - 2.0f * __fdividef(1.0f, 1.0f + __expf(2.0f * x));
}

#define TILE_B   16384          // 128 x 64 fp16
#define BUF_B    (3 * TILE_B)   // A, Wh, Wl
#define N_STAGE  4
#define SMEM_TOT (1024 + N_STAGE * BUF_B)  // 197632

// ------------------------------------------------------------------
// Fused GEMM + LSTM-cell step kernel.
// CTA: 128 batches x 128 gate-cols (32 units). 8 warps (2 M x 4 N). BK=64.
// gates col n -> W row (n&3)*H + u0 + (n>>2)  (gate-interleaved N)
// ------------------------------------------------------------------
__global__ void __launch_bounds__(256, 1)
lstm_step(int layer, int t, int pp,
          const float* __restrict__ bih, const float* __restrict__ bhh) {
    extern __shared__ __align__(16) char smem[];
    const u32 sb = smem_to_u32(smem) + 1024;
    const int tid = threadIdx.x;
    const int lane = tid & 31;
    const int wid = tid >> 5;
    const int wm = wid >> 2;          // 0..1 -> 64 rows
    const int wn = wid & 3;           // 0..3 -> 32 cols
    const int u0 = blockIdx.x * 32;
    const int m0 = blockIdx.y * 128;

    float* sbias = (float*)smem;      // [128]
    if (tid < 128) {
        const int wr = (tid & 3) * H_DIM + u0 + (tid >> 2);
        sbias[tid] = bih[wr] + bhh[wr];
    }

    // loader assignment: row r (0..127), chunk block h4 (0..3 or 4..7)
    const int r  = tid >> 1;
    const int h4 = (tid & 1) * 4;
    const int wrow = (r & 3) * H_DIM + u0 + (r >> 2);

    const __half *Ar[2], *Wr[2];
    int wK[2], nc0;
    if (layer == 0) {
        Ar[0] = g_x + (size_t)(m0 + r) * (T_DIM * DPAD) + (size_t)t * DPAD;
        Wr[0] = g_wih0 + (size_t)wrow * 2 * DPAD;
        wK[0] = DPAD;
        nc0 = DPAD / 64;  // 5
        Ar[1] = g_h0b[pp] + (size_t)(m0 + r) * H_DIM;
        Wr[1] = g_whh0 + (size_t)wrow * 2 * H_DIM;
    } else {
        Ar[0] = g_h0b[pp ^ 1] + (size_t)(m0 + r) * H_DIM;  // h0 of this step
        Wr[0] = g_wih1 + (size_t)wrow * 2 * H_DIM;
        wK[0] = H_DIM;
        nc0 = H_DIM / 64;  // 16
        Ar[1] = g_h1b[pp] + (size_t)(m0 + r) * H_DIM;
        Wr[1] = g_whh1 + (size_t)wrow * 2 * H_DIM;
    }
    wK[1] = H_DIM;
    const int NC = nc0 + H_DIM / 64;

    float acc[4][4][4];
#pragma unroll
    for (int mi = 0; mi < 4; mi++)
#pragma unroll
        for (int nf = 0; nf < 4; nf++)
#pragma unroll
            for (int q = 0; q < 4; q++) acc[mi][nf][q] = 0.0f;

    auto ldchunk = [&](int c, int buf) {
        const int sg = (c < nc0) ? 0 : 1;
        const int k0 = ((c < nc0) ? c : (c - nc0)) * 64;
        const __half* pa = Ar[sg];
        const __half* pw = Wr[sg];
        const int Ksz = wK[sg];
        const u32 d = sb + (u32)buf * BUF_B;
#pragma unroll
        for (int j = 0; j < 4; j++) {
            const int q = h4 + j;
            const u32 so = swz((u32)r, (u32)q);
            const int e = k0 + q * 8;
            cp16(d + so, pa + e);
            cp16(d + TILE_B + so, pw + e);
            cp16(d + 2 * TILE_B + so, pw + Ksz + e);
        }
    };

    ldchunk(0, 0); CP_COMMIT();
    ldchunk(1, 1); CP_COMMIT();

    for (int c = 0; c < NC; c++) {
        if (c + 2 < NC) { ldchunk(c + 2, (c + 2) & 3); CP_COMMIT(); CP_WAIT2(); }
        else if (c + 1 < NC) { CP_WAIT1(); }
        else { CP_WAIT0(); }
        __syncthreads();  // chunk c visible; also fences buffer reuse (dist 4)

        const u32 bA  = sb + (u32)(c & 3) * BUF_B;
        const u32 bWh = bA + TILE_B;
        const u32 bWl = bA + 2 * TILE_B;

#pragma unroll
        for (int kk = 0; kk < 4; kk++) {
            u32 a[4][4], wh[2][4], wl[2][4];
            const u32 aq = 2 * kk + (lane >> 4);
#pragma unroll
            for (int mi = 0; mi < 4; mi++) {
                const u32 row = wm * 64 + mi * 16 + (lane & 15);
                ldsm4(bA + swz(row, aq), a[mi]);
            }
            const u32 wq = 2 * kk + ((lane >> 3) & 1);
#pragma unroll
            for (int nf2 = 0; nf2 < 2; nf2++) {
                const u32 row = wn * 32 + nf2 * 16 + (lane & 7) + ((lane >> 4) << 3);
                const u32 off = swz(row, wq);
                ldsm4(bWh + off, wh[nf2]);
                ldsm4(bWl + off, wl[nf2]);
            }
#pragma unroll
            for (int mi = 0; mi < 4; mi++)
#pragma unroll
                for (int nf = 0; nf < 4; nf++) {
                    const u32* H = wh[nf >> 1] + (nf & 1) * 2;
                    const u32* L = wl[nf >> 1] + (nf & 1) * 2;
                    mma_f16(acc[mi][nf], a[mi], H[0], H[1]);  // a * W_hi
                    mma_f16(acc[mi][nf], a[mi], L[0], L[1]);  // a * W_lo
                }
        }
    }

    // ---------------- fused LSTM epilogue ----------------
    float* cmem = layer ? g_c1 : g_c0;
    __half* hout = (layer ? g_h1b[pp ^ 1] : g_h0b[pp ^ 1]);
    const bool owner = ((lane & 1) == 0);
    const int cc = 2 * (lane & 3);

#pragma unroll
    for (int mi = 0; mi < 4; mi++)
#pragma unroll
        for (int nf = 0; nf < 4; nf++) {
            float v0 = acc[mi][nf][0], v1 = acc[mi][nf][1];
            float v2 = acc[mi][nf][2], v3 = acc[mi][nf][3];
            const float p0 = __shfl_xor_sync(0xffffffffu, v0, 1);
            const float p1 = __shfl_xor_sync(0xffffffffu, v1, 1);
            const float p2 = __shfl_xor_sync(0xffffffffu, v2, 1);
            const float p3 = __shfl_xor_sync(0xffffffffu, v3, 1);
            if (owner) {
                const int nl = wn * 32 + nf * 8 + cc;
                const int ucol = u0 + (nl >> 2);
                const float bi = sbias[nl], bf = sbias[nl + 1];
                const float bg = sbias[nl + 2], bo = sbias[nl + 3];
                const int rowa = m0 + wm * 64 + mi * 16 + (lane >> 2);
#pragma unroll
                for (int rh = 0; rh < 2; rh++) {
                    const int b = rowa + rh * 8;
                    const float iv = (rh ? v2 : v0) + bi;
                    const float fv = (rh ? v3 : v1) + bf;
                    const float gv = (rh ? p2 : p0) + bg;
                    const float ov = (rh ? p3 : p1) + bo;
                    const size_t ci = (size_t)b * H_DIM + ucol;
                    const float cold = cmem[ci];
                    const float cn = sigf(fv) * cold + sigf(iv) * tanhf_(gv);
                    const float hn = sigf(ov) * tanhf_(cn);
                    cmem[ci] = cn;
                    hout[ci] = __float2half(hn);
                    if (layer) g_acc[ci] += hn;
                }
            }
        }
}

// ------------------------------------------------------------------
// Conversion / init / finalize kernels
// ------------------------------------------------------------------
__global__ void conv_w_k(const float* __restrict__ W, int K, int Kp, int sel) {
    __half* out = (sel == 0) ? g_wih0 : (sel == 1) ? g_whh0
                 : (sel == 2) ? g_wih1 : g_whh1;
    const size_t n = (size_t)4 * H_DIM * Kp;
    for (size_t i = (size_t)blockIdx.x * blockDim.x + threadIdx.x; i < n;
         i += (size_t)gridDim.x * blockDim.x) {
        const size_t row = i / Kp;
        const int k = (int)(i % Kp);
        const float v = (k < K) ? W[row * K + k] : 0.0f;
        const __half hi = __float2half(v);
        out[row * 2 * Kp + k] = hi;
        out[row * 2 * Kp + Kp + k] = __float2half(v - __half2float(hi));
    }
}

__global__ void conv_x_k(const float* __restrict__ x) {
    const size_t n = (size_t)B_DIM * T_DIM * DPAD;
    for (size_t i = (size_t)blockIdx.x * blockDim.x + threadIdx.x; i < n;
         i += (size_t)gridDim.x * blockDim.x) {
        const size_t bt = i / DPAD;
        const int k = (int)(i % DPAD);
        g_x[bt * DPAD + k] = __float2half((k < D_DIM) ? x[bt * D_DIM + k] : 0.0f);
    }
}

__global__ void init_k() {
    const size_t nf = (size_t)B_DIM * H_DIM;
    const size_t stride = (size_t)gridDim.x * blockDim.x;
    for (size_t i = (size_t)blockIdx.x * blockDim.x + threadIdx.x; i < nf; i += stride) {
        g_h0b[0][i] = __float2half(0.0f);
        g_h1b[0][i] = __float2half(0.0f);
        g_c0[i] = 0.0f; g_c1[i] = 0.0f; g_acc[i] = 0.0f;
    }
}

__global__ void finalize_k(const float* __restrict__ Wdec,
                           const float* __restrict__ bdec, float* __restrict__ out) {
    const int b = blockIdx.x;
    const int tid = threadIdx.x;  // 128
    float p = 0.0f;
    for (int u = tid; u < H_DIM; u += 128)
        p += g_acc[(size_t)b * H_DIM + u] * Wdec[u];
#pragma unroll
    for (int o = 16; o; o >>= 1) p += __shfl_down_sync(0xffffffffu, p, o);
    __shared__ float red[4];
    if ((tid & 31) == 0) red[tid >> 5] = p;
    __syncthreads();
    if (tid == 0)
        out[b] = (red[0] + red[1] + red[2] + red[3]) * (1.0f / (float)T_DIM) + bdec[0];
}

// ------------------------------------------------------------------
extern "C" void kernel_launch(void* const* d_in, const int* in_sizes, int n_in,
                              void* d_out, int out_size) {
    const float* x    = (const float*)d_in[0];
    const float* Wih0 = (const float*)d_in[1];
    const float* Whh0 = (const float*)d_in[2];
    const float* bih0 = (const float*)d_in[3];
    const float* bhh0 = (const float*)d_in[4];
    const float* Wih1 = (const float*)d_in[5];
    const float* Whh1 = (const float*)d_in[6];
    const float* bih1 = (const float*)d_in[7];
    const float* bhh1 = (const float*)d_in[8];
    const float* Wdec = (const float*)d_in[9];
    const float* bdec = (const float*)d_in[10];
    float* out = (float*)d_out;

    cudaFuncSetAttribute(lstm_step, cudaFuncAttributeMaxDynamicSharedMemorySize, SMEM_TOT);

    init_k<<<512, 256>>>();
    conv_w_k<<<1024, 256>>>(Wih0, D_DIM, DPAD, 0);
    conv_w_k<<<2048, 256>>>(Whh0, H_DIM, H_DIM, 1);
    conv_w_k<<<2048, 256>>>(Wih1, H_DIM, H_DIM, 2);
    conv_w_k<<<2048, 256>>>(Whh1, H_DIM, H_DIM, 3);
    conv_x_k<<<4096, 256>>>(x);

    dim3 grid(32, 4);  // 32 unit-tiles x 4 batch-tiles = 128 CTAs
    for (int t = 0; t < T_DIM; ++t) {
        const int pp = t & 1;
        lstm_step<<<grid, 256, SMEM_TOT>>>(0, t, pp, bih0, bhh0);
        lstm_step<<<grid, 256, SMEM_TOT>>>(1, t, pp, bih1, bhh1);
    }
    finalize_k<<<B_DIM, 128>>>(Wdec, bdec, out);
}

// round 5
// speedup vs baseline: 11.6428x; 1.4287x over previous
#include <cuda_runtime.h>
#include <cuda_fp16.h>
#include <cstdint>

#define B_DIM 512
#define T_DIM 128
#define D_DIM 300
#define DPAD  320
#define H_DIM 1024

typedef uint32_t u32;

// ------------------------------------------------------------------
// Persistent device buffers (static globals; no runtime allocation)
// Activations and weights: single fp16.
// ------------------------------------------------------------------
__device__ __align__(16) __half g_x[(size_t)B_DIM * T_DIM * DPAD];
__device__ __align__(16) __half g_wih0[(size_t)4 * H_DIM * DPAD];
__device__ __align__(16) __half g_whh0[(size_t)4 * H_DIM * H_DIM];
__device__ __align__(16) __half g_wih1[(size_t)4 * H_DIM * H_DIM];
__device__ __align__(16) __half g_whh1[(size_t)4 * H_DIM * H_DIM];
__device__ __align__(16) __half g_h0b[2][(size_t)B_DIM * H_DIM];
__device__ __align__(16) __half g_h1b[2][(size_t)B_DIM * H_DIM];
__device__ __align__(16) float g_c0[(size_t)B_DIM * H_DIM];
__device__ __align__(16) float g_c1[(size_t)B_DIM * H_DIM];
__device__ __align__(16) float g_acc[(size_t)B_DIM * H_DIM];

// ------------------------------------------------------------------
// Helpers (sm_80-compatible: cp.async / ldmatrix / mma.sync)
// ------------------------------------------------------------------
__device__ __forceinline__ u32 smem_to_u32(const void* p) {
    u32 a;
    asm("{ .reg .u64 t; cvta.to.shared.u64 t, %1; cvt.u32.u64 %0, t; }" : "=r"(a) : "l"(p));
    return a;
}
__device__ __forceinline__ void cp16(u32 s, const void* g) {
    asm volatile("cp.async.cg.shared.global [%0], [%1], 16;" :: "r"(s), "l"(g));
}
#define CP_COMMIT() asm volatile("cp.async.commit_group;" ::: "memory")
#define CP_WAIT2()  asm volatile("cp.async.wait_group 2;" ::: "memory")
#define CP_WAIT1()  asm volatile("cp.async.wait_group 1;" ::: "memory")
#define CP_WAIT0()  asm volatile("cp.async.wait_group 0;" ::: "memory")

__device__ __forceinline__ void ldsm4(u32 addr, u32* r) {
    asm volatile("ldmatrix.sync.aligned.m8n8.x4.shared.b16 {%0,%1,%2,%3}, [%4];"
                 : "=r"(r[0]), "=r"(r[1]), "=r"(r[2]), "=r"(r[3]) : "r"(addr));
}
__device__ __forceinline__ void mma_f16(float* d, const u32* a, u32 b0, u32 b1) {
    asm volatile("mma.sync.aligned.m16n8k16.row.col.f32.f16.f16.f32 "
                 "{%0,%1,%2,%3}, {%4,%5,%6,%7}, {%8,%9}, {%0,%1,%2,%3};"
                 : "+f"(d[0]), "+f"(d[1]), "+f"(d[2]), "+f"(d[3])
                 : "r"(a[0]), "r"(a[1]), "r"(a[2]), "r"(a[3]), "r"(b0), "r"(b1));
}

// SMEM tile: [128 rows][64 fp16] = 128B/row = 8 x 16B chunks; swizzle q^(row&7)
__device__ __forceinline__ u32 swz(u32 row, u32 q) {
    return row * 128u + ((q ^ (row & 7u)) << 4);
}

__device__ __forceinline__ float sigf(float x) { return __fdividef(1.0f, 1.0f + __expf(-x)); }
__device__ __forceinline__ float tanhf_(float x) {
    return 1.0f - 2.0f * __fdividef(1.0f, 1.0f + __expf(2.0f * x));
}

#define TILE_B   16384          // 128 x 64 fp16
#define BUF_B    (2 * TILE_B)   // A, W
#define N_STAGE  4
#define SMEM_TOT (1024 + N_STAGE * BUF_B)  // 132096

// ------------------------------------------------------------------
// Fused GEMM + LSTM-cell step kernel.
// CTA: 128 batches x 128 gate-cols (32 units). 8 warps (2 M x 4 N). BK=64.
// gates col n -> W row (n&3)*H + u0 + (n>>2)  (gate-interleaved N)
// ------------------------------------------------------------------
__global__ void __launch_bounds__(256, 1)
lstm_step(int layer, int t, int pp,
          const float* __restrict__ bih, const float* __restrict__ bhh) {
    extern __shared__ __align__(16) char smem[];
    const u32 sb = smem_to_u32(smem) + 1024;
    const int tid = threadIdx.x;
    const int lane = tid & 31;
    const int wid = tid >> 5;
    const int wm = wid >> 2;          // 0..1 -> 64 rows
    const int wn = wid & 3;           // 0..3 -> 32 cols
    const int u0 = blockIdx.x * 32;
    const int m0 = blockIdx.y * 128;

    float* sbias = (float*)smem;      // [128]
    if (tid < 128) {
        const int wr = (tid & 3) * H_DIM + u0 + (tid >> 2);
        sbias[tid] = bih[wr] + bhh[wr];
    }

    // loader assignment: row r (0..127), chunk block h4 (0..3 or 4..7)
    const int r  = tid >> 1;
    const int h4 = (tid & 1) * 4;
    const int wrow = (r & 3) * H_DIM + u0 + (r >> 2);

    const __half *Ar[2], *Wr[2];
    int nc0;
    if (layer == 0) {
        Ar[0] = g_x + (size_t)(m0 + r) * (T_DIM * DPAD) + (size_t)t * DPAD;
        Wr[0] = g_wih0 + (size_t)wrow * DPAD;
        nc0 = DPAD / 64;  // 5
        Ar[1] = g_h0b[pp] + (size_t)(m0 + r) * H_DIM;
        Wr[1] = g_whh0 + (size_t)wrow * H_DIM;
    } else {
        Ar[0] = g_h0b[pp ^ 1] + (size_t)(m0 + r) * H_DIM;  // h0 of this step
        Wr[0] = g_wih1 + (size_t)wrow * H_DIM;
        nc0 = H_DIM / 64;  // 16
        Ar[1] = g_h1b[pp] + (size_t)(m0 + r) * H_DIM;
        Wr[1] = g_whh1 + (size_t)wrow * H_DIM;
    }
    const int NC = nc0 + H_DIM / 64;

    float acc[4][4][4];
#pragma unroll
    for (int mi = 0; mi < 4; mi++)
#pragma unroll
        for (int nf = 0; nf < 4; nf++)
#pragma unroll
            for (int q = 0; q < 4; q++) acc[mi][nf][q] = 0.0f;

    auto ldchunk = [&](int c, int buf) {
        const int sg = (c < nc0) ? 0 : 1;
        const int k0 = ((c < nc0) ? c : (c - nc0)) * 64;
        const __half* pa = Ar[sg];
        const __half* pw = Wr[sg];
        const u32 d = sb + (u32)buf * BUF_B;
#pragma unroll
        for (int j = 0; j < 4; j++) {
            const int q = h4 + j;
            const u32 so = swz((u32)r, (u32)q);
            const int e = k0 + q * 8;
            cp16(d + so, pa + e);
            cp16(d + TILE_B + so, pw + e);
        }
    };

    ldchunk(0, 0); CP_COMMIT();
    ldchunk(1, 1); CP_COMMIT();

    for (int c = 0; c < NC; c++) {
        if (c + 2 < NC) { ldchunk(c + 2, (c + 2) & 3); CP_COMMIT(); CP_WAIT2(); }
        else if (c + 1 < NC) { CP_WAIT1(); }
        else { CP_WAIT0(); }
        __syncthreads();  // chunk c visible; also fences buffer reuse (dist 4)

        const u32 bA = sb + (u32)(c & 3) * BUF_B;
        const u32 bW = bA + TILE_B;

#pragma unroll
        for (int kk = 0; kk < 4; kk++) {
            u32 a[4][4], w[2][4];
            const u32 aq = 2 * kk + (lane >> 4);
#pragma unroll
            for (int mi = 0; mi < 4; mi++) {
                const u32 row = wm * 64 + mi * 16 + (lane & 15);
                ldsm4(bA + swz(row, aq), a[mi]);
            }
            const u32 wq = 2 * kk + ((lane >> 3) & 1);
#pragma unroll
            for (int nf2 = 0; nf2 < 2; nf2++) {
                const u32 row = wn * 32 + nf2 * 16 + (lane & 7) + ((lane >> 4) << 3);
                ldsm4(bW + swz(row, wq), w[nf2]);
            }
#pragma unroll
            for (int mi = 0; mi < 4; mi++)
#pragma unroll
                for (int nf = 0; nf < 4; nf++) {
                    const u32* W = w[nf >> 1] + (nf & 1) * 2;
                    mma_f16(acc[mi][nf], a[mi], W[0], W[1]);
                }
        }
    }

    // ---------------- fused LSTM epilogue ----------------
    float* cmem = layer ? g_c1 : g_c0;
    __half* hout = (layer ? g_h1b[pp ^ 1] : g_h0b[pp ^ 1]);
    const bool owner = ((lane & 1) == 0);
    const int cc = 2 * (lane & 3);

#pragma unroll
    for (int mi = 0; mi < 4; mi++)
#pragma unroll
        for (int nf = 0; nf < 4; nf++) {
            float v0 = acc[mi][nf][0], v1 = acc[mi][nf][1];
            float v2 = acc[mi][nf][2], v3 = acc[mi][nf][3];
            const float p0 = __shfl_xor_sync(0xffffffffu, v0, 1);
            const float p1 = __shfl_xor_sync(0xffffffffu, v1, 1);
            const float p2 = __shfl_xor_sync(0xffffffffu, v2, 1);
            const float p3 = __shfl_xor_sync(0xffffffffu, v3, 1);
            if (owner) {
                const int nl = wn * 32 + nf * 8 + cc;
                const int ucol = u0 + (nl >> 2);
                const float bi = sbias[nl], bf = sbias[nl + 1];
                const float bg = sbias[nl + 2], bo = sbias[nl + 3];
                const int rowa = m0 + wm * 64 + mi * 16 + (lane >> 2);
#pragma unroll
                for (int rh = 0; rh < 2; rh++) {
                    const int b = rowa + rh * 8;
                    const float iv = (rh ? v2 : v0) + bi;
                    const float fv = (rh ? v3 : v1) + bf;
                    const float gv = (rh ? p2 : p0) + bg;
                    const float ov = (rh ? p3 : p1) + bo;
                    const size_t ci = (size_t)b * H_DIM + ucol;
                    const float cold = cmem[ci];
                    const float cn = sigf(fv) * cold + sigf(iv) * tanhf_(gv);
                    const float hn = sigf(ov) * tanhf_(cn);
                    cmem[ci] = cn;
                    hout[ci] = __float2half(hn);
                    if (layer) g_acc[ci] += hn;
                }
            }
        }
}

// ------------------------------------------------------------------
// Conversion / init / finalize kernels
// ------------------------------------------------------------------
__global__ void conv_w_k(const float* __restrict__ W, int K, int Kp, int sel) {
    __half* out = (sel == 0) ? g_wih0 : (sel == 1) ? g_whh0
                 : (sel == 2) ? g_wih1 : g_whh1;
    const size_t n = (size_t)4 * H_DIM * Kp;
    for (size_t i = (size_t)blockIdx.x * blockDim.x + threadIdx.x; i < n;
         i += (size_t)gridDim.x * blockDim.x) {
        const size_t row = i / Kp;
        const int k = (int)(i % Kp);
        out[row * Kp + k] = __float2half((k < K) ? W[row * K + k] : 0.0f);
    }
}

__global__ void conv_x_k(const float* __restrict__ x) {
    const size_t n = (size_t)B_DIM * T_DIM * DPAD;
    for (size_t i = (size_t)blockIdx.x * blockDim.x + threadIdx.x; i < n;
         i += (size_t)gridDim.x * blockDim.x) {
        const size_t bt = i / DPAD;
        const int k = (int)(i % DPAD);
        g_x[bt * DPAD + k] = __float2half((k < D_DIM) ? x[bt * D_DIM + k] : 0.0f);
    }
}

__global__ void init_k() {
    const size_t nf = (size_t)B_DIM * H_DIM;
    const size_t stride = (size_t)gridDim.x * blockDim.x;
    for (size_t i = (size_t)blockIdx.x * blockDim.x + threadIdx.x; i < nf; i += stride) {
        g_h0b[0][i] = __float2half(0.0f);
        g_h1b[0][i] = __float2half(0.0f);
        g_c0[i] = 0.0f; g_c1[i] = 0.0f; g_acc[i] = 0.0f;
    }
}

__global__ void finalize_k(const float* __restrict__ Wdec,
                           const float* __restrict__ bdec, float* __restrict__ out) {
    const int b = blockIdx.x;
    const int tid = threadIdx.x;  // 128
    float p = 0.0f;
    for (int u = tid; u < H_DIM; u += 128)
        p += g_acc[(size_t)b * H_DIM + u] * Wdec[u];
#pragma unroll
    for (int o = 16; o; o >>= 1) p += __shfl_down_sync(0xffffffffu, p, o);
    __shared__ float red[4];
    if ((tid & 31) == 0) red[tid >> 5] = p;
    __syncthreads();
    if (tid == 0)
        out[b] = (red[0] + red[1] + red[2] + red[3]) * (1.0f / (float)T_DIM) + bdec[0];
}

// ------------------------------------------------------------------
extern "C" void kernel_launch(void* const* d_in, const int* in_sizes, int n_in,
                              void* d_out, int out_size) {
    const float* x    = (const float*)d_in[0];
    const float* Wih0 = (const float*)d_in[1];
    const float* Whh0 = (const float*)d_in[2];
    const float* bih0 = (const float*)d_in[3];
    const float* bhh0 = (const float*)d_in[4];
    const float* Wih1 = (const float*)d_in[5];
    const float* Whh1 = (const float*)d_in[6];
    const float* bih1 = (const float*)d_in[7];
    const float* bhh1 = (const float*)d_in[8];
    const float* Wdec = (const float*)d_in[9];
    const float* bdec = (const float*)d_in[10];
    float* out = (float*)d_out;

    cudaFuncSetAttribute(lstm_step, cudaFuncAttributeMaxDynamicSharedMemorySize, SMEM_TOT);

    init_k<<<512, 256>>>();
    conv_w_k<<<1024, 256>>>(Wih0, D_DIM, DPAD, 0);
    conv_w_k<<<2048, 256>>>(Whh0, H_DIM, H_DIM, 1);
    conv_w_k<<<2048, 256>>>(Wih1, H_DIM, H_DIM, 2);
    conv_w_k<<<2048, 256>>>(Whh1, H_DIM, H_DIM, 3);
    conv_x_k<<<4096, 256>>>(x);

    dim3 grid(32, 4);  // 32 unit-tiles x 4 batch-tiles = 128 CTAs
    for (int t = 0; t < T_DIM; ++t) {
        const int pp = t & 1;
        lstm_step<<<grid, 256, SMEM_TOT>>>(0, t, pp, bih0, bhh0);
        lstm_step<<<grid, 256, SMEM_TOT>>>(1, t, pp, bih1, bhh1);
    }
    finalize_k<<<B_DIM, 128>>>(Wdec, bdec, out);
}